// round 7
// baseline (speedup 1.0000x reference)
#include <cuda_runtime.h>
#include <cuda_fp16.h>
#include <cstdint>

#define B    8
#define S    1024
#define D    96
#define G    8
#define MTOT (D*D)          // 9216
#define ND   (B*D)          // 768
#define DPAD 100
#define LN_EPS 1e-5f
#define TWO_PI 6.283185307179586f

// ---------------- scratch (device globals; no allocation allowed) ----------
__device__ __half g_W   [S*MTOT];      // W[s, i*96+j] fp16            (18 MB)
__device__ float  g_A   [S*ND];        // (T+Z0) as A[s, b*96+i]       (3 MB)
__device__ float  g_part[4*S*ND];      // split-K partials             (12.6 MB)

// ---------------- packed f32x2 helpers (sm_103) -----------------------------
__device__ __forceinline__ unsigned long long splat2(float a) {
    unsigned long long r;
    asm("mov.b64 %0, {%1, %1};" : "=l"(r) : "f"(a));
    return r;
}
__device__ __forceinline__ void fma2(unsigned long long& d,
                                     unsigned long long a,
                                     unsigned long long b) {
    asm("fma.rn.f32x2 %0, %1, %2, %0;" : "+l"(d) : "l"(a), "l"(b));
}
__device__ __forceinline__ float2 unpack2(unsigned long long v) {
    float lo, hi;
    asm("mov.b64 {%0, %1}, %2;" : "=f"(lo), "=f"(hi) : "l"(v));
    return make_float2(lo, hi);
}
__device__ __forceinline__ uint32_t s2u(const void* p) {
    uint32_t a;
    asm("{ .reg .u64 t; cvta.to.shared.u64 t, %1; cvt.u32.u64 %0, t; }" : "=r"(a) : "l"(p));
    return a;
}
__device__ __forceinline__ void cp16(uint32_t smem, const void* g) {
    asm volatile("cp.async.ca.shared.global [%0], [%1], 16;" :: "r"(smem), "l"(g));
}
#define CP_COMMIT() asm volatile("cp.async.commit_group;")
template <int N>
__device__ __forceinline__ void cp_wait() {
    asm volatile("cp.async.wait_group %0;" :: "n"(N));
}

// ---------------- K2: W[s,m] = sum_g P[m*8+g] * cos(2*pi*s/(8m+g+2)) -------
#define SCHUNK 64
__global__ void k2_basis(const float* __restrict__ P)
{
    const int gidx  = blockIdx.x*blockDim.x + threadIdx.x;
    const int m     = gidx % MTOT;
    const int chunk = gidx / MTOT;
    const int s0    = chunk * SCHUNK;

    float kg[G], c0[G], c1[G], Pv[G];
#pragma unroll
    for (int g = 0; g < G; ++g) {
        const int p    = m*G + g + 2;
        const float fp = (float)p;
        kg[g] = 2.f * cosf(TWO_PI / fp);
        const int r0  = s0 % p;
        const int rm1 = (s0 + p - 1) % p;
        c1[g] = cosf(TWO_PI * (float)r0  / fp);
        c0[g] = cosf(TWO_PI * (float)rm1 / fp);
        Pv[g] = P[m*G + g];
    }

    __half* Wp = g_W + (size_t)s0*MTOT + m;
    for (int s = 0; s < SCHUNK; ++s) {
        float w = 0.f;
#pragma unroll
        for (int g = 0; g < G; ++g) w = fmaf(Pv[g], c1[g], w);
        Wp[(size_t)s*MTOT] = __float2half(w);
#pragma unroll
        for (int g = 0; g < G; ++g) {
            const float cn = fmaf(kg[g], c1[g], -c0[g]);
            c0[g] = c1[g];
            c1[g] = cn;
        }
    }
}

// ---------------- K13: fused project + LN + per-s mixing + residual --------
// thread layout tid = i*8 + b: smem reads become broadcast within warps.
__global__ __launch_bounds__(768) void k13_fused(const float* __restrict__ x,
                                                 const float* __restrict__ M,
                                                 const float* __restrict__ gamma,
                                                 const float* __restrict__ beta)
{
    const int s   = blockIdx.x;
    const int tid = threadIdx.x;
    const int i   = tid >> 3;          // 0..95
    const int b   = tid & 7;           // 0..7

    __shared__ __align__(16) float sBuf[D*DPAD];    // M rows, then W rows (padded)
    __shared__ __align__(16) float sx  [B*DPAD];    // x[b][j] padded
    __shared__ __align__(16) float sZ  [B*DPAD];    // Z[b][j] padded
    __shared__ float sS1[24][8], sS2[24][8];

    // prefetch W row-chunk as fp16 pairs (LDGs fly during phase 1)
    __half2 wreg[6];
    const __half2* Wp = reinterpret_cast<const __half2*>(g_W + (size_t)s*MTOT);
#pragma unroll
    for (int r = 0; r < 6; ++r) wreg[r] = Wp[tid + r*768];

    // cooperative coalesced stage of x rows (all 8 b at this s)
    {
        const int bb = tid / D, jj = tid % D;
        sx[bb*DPAD + jj] = x[((size_t)bb*S + s)*D + jj];
    }
    // stage M row-major padded
#pragma unroll
    for (int r = 0; r < 12; ++r) {
        const int f = tid + r*768;
        sBuf[(f / D)*DPAD + (f % D)] = M[f];
    }
    __syncthreads();

    // Z0[b,i] = dot(M[i,:], x[b,:]) — M reads broadcast x8, x reads broadcast x4
    float z0 = 0.f;
    {
        const float4* mr = reinterpret_cast<const float4*>(sBuf + i*DPAD);
        const float4* xr = reinterpret_cast<const float4*>(sx + b*DPAD);
#pragma unroll
        for (int j4 = 0; j4 < D/4; ++j4) {
            const float4 m4 = mr[j4];
            const float4 x4 = xr[j4];
            z0 = fmaf(m4.x, x4.x, z0);
            z0 = fmaf(m4.y, x4.y, z0);
            z0 = fmaf(m4.z, x4.z, z0);
            z0 = fmaf(m4.w, x4.w, z0);
        }
    }

    // LayerNorm over i per b: warp holds 4 i x 8 b; i-bits are lane bits 3,4
    float s1 = z0, s2 = z0*z0;
    s1 += __shfl_xor_sync(0xffffffffu, s1, 8);
    s2 += __shfl_xor_sync(0xffffffffu, s2, 8);
    s1 += __shfl_xor_sync(0xffffffffu, s1, 16);
    s2 += __shfl_xor_sync(0xffffffffu, s2, 16);
    const int w = tid >> 5, lane = tid & 31;
    if (lane < 8) { sS1[w][lane] = s1; sS2[w][lane] = s2; }
    __syncthreads();
    float t1 = 0.f, t2 = 0.f;
#pragma unroll
    for (int ww = 0; ww < 24; ++ww) { t1 += sS1[ww][b]; t2 += sS2[ww][b]; }
    const float mu  = t1 * (1.f/D);
    const float rstd = rsqrtf(t2 * (1.f/D) - mu*mu + LN_EPS);
    sZ[b*DPAD + i] = (z0 - mu)*rstd*gamma[i] + beta[i];

    // overwrite sBuf with W rows (fp16 -> f32, padded row-major)
#pragma unroll
    for (int r = 0; r < 6; ++r) {
        const int e0  = 2*(tid + r*768);
        const int row = e0 / D, col = e0 % D;
        const float2 v = __half22float2(wreg[r]);
        sBuf[row*DPAD + col]     = v.x;
        sBuf[row*DPAD + col + 1] = v.y;
    }
    __syncthreads();

    // T[b,i] = dot(W[s,i,:], Z[b,:]);  A = T + Z0
    float acc = 0.f;
    {
        const float4* wr = reinterpret_cast<const float4*>(sBuf + i*DPAD);
        const float4* zr = reinterpret_cast<const float4*>(sZ + b*DPAD);
#pragma unroll
        for (int j4 = 0; j4 < D/4; ++j4) {
            const float4 w4 = wr[j4];
            const float4 z4 = zr[j4];
            acc = fmaf(w4.x, z4.x, acc);
            acc = fmaf(w4.y, z4.y, acc);
            acc = fmaf(w4.z, z4.z, acc);
            acc = fmaf(w4.w, z4.w, acc);
        }
    }
    g_A[(size_t)s*ND + b*D + i] = acc + z0;
}

// ---------------- K4: split-K GEMM, 256x64 tile, 16x4 micro, f32x2 + cp.async
#define BT 256
#define BN 64
#define BK 16
#define KSPLIT 4
#define KCH (S/KSPLIT)     // 256
#define NIT (KCH/BK)       // 16
__global__ __launch_bounds__(256, 2) void k4_gemm(const float* __restrict__ L)
{
    __shared__ __align__(16) float Ls[2][BK][BT];   // 2 * 16 KB
    __shared__ __align__(16) float As[2][BK][BN];   // 2 * 4 KB
    const int tid = threadIdx.x;
    const int n0  = blockIdx.x * BN;
    const int t0  = blockIdx.y * BT;
    const int z   = blockIdx.z;
    const int tx  = tid & 15;          // n micro (4 cols)
    const int ty  = tid >> 4;          // t micro (16 rows = 8 packed pairs)
    const int kbeg = z * KCH;

    const uint32_t sLs = s2u(&Ls[0][0][0]);
    const uint32_t sAs = s2u(&As[0][0][0]);
    const int akk = tid >> 4, ac = (tid & 15) * 4;   // As: 1 cp16/thread

    auto load_chunk = [&](int it, int buf) {
        const int ks = kbeg + it*BK;
#pragma unroll
        for (int q = 0; q < 4; ++q) {                // Ls: 4 cp16/thread
            const int f  = tid + q*256;              // float4 index 0..1023
            const int kk = f >> 6, c4 = f & 63;
            cp16(sLs + (uint32_t)(buf*BK*BT + kk*BT + c4*4)*4,
                 &L[(size_t)(ks+kk)*S + t0 + c4*4]);
        }
        cp16(sAs + (uint32_t)(buf*BK*BN + akk*BN + ac)*4,
             &g_A[(size_t)(ks+akk)*ND + n0 + ac]);
        CP_COMMIT();
    };

    unsigned long long acc2[8][4];
#pragma unroll
    for (int u = 0; u < 8; ++u)
#pragma unroll
        for (int v = 0; v < 4; ++v) acc2[u][v] = 0ull;

    load_chunk(0, 0);
    for (int it = 0; it < NIT; ++it) {
        const int cur = it & 1;
        if (it + 1 < NIT) { load_chunk(it + 1, cur ^ 1); cp_wait<1>(); }
        else              { cp_wait<0>(); }
        __syncthreads();
#pragma unroll
        for (int kk = 0; kk < BK; ++kk) {
            const ulonglong2 lp0 = *reinterpret_cast<const ulonglong2*>(&Ls[cur][kk][ty*16]);
            const ulonglong2 lp1 = *reinterpret_cast<const ulonglong2*>(&Ls[cur][kk][ty*16+4]);
            const ulonglong2 lp2 = *reinterpret_cast<const ulonglong2*>(&Ls[cur][kk][ty*16+8]);
            const ulonglong2 lp3 = *reinterpret_cast<const ulonglong2*>(&Ls[cur][kk][ty*16+12]);
            const unsigned long long lp[8] =
                {lp0.x, lp0.y, lp1.x, lp1.y, lp2.x, lp2.y, lp3.x, lp3.y};
            const float4 a4 = *reinterpret_cast<const float4*>(&As[cur][kk][tx*4]);
            const unsigned long long ap[4] =
                {splat2(a4.x), splat2(a4.y), splat2(a4.z), splat2(a4.w)};
#pragma unroll
            for (int u = 0; u < 8; ++u)
#pragma unroll
                for (int v = 0; v < 4; ++v)
                    fma2(acc2[u][v], lp[u], ap[v]);
        }
        __syncthreads();
    }

    float* base = g_part + (size_t)z*(S*ND);
#pragma unroll
    for (int u = 0; u < 8; ++u) {
        float2 r0 = unpack2(acc2[u][0]);
        float2 r1 = unpack2(acc2[u][1]);
        float2 r2 = unpack2(acc2[u][2]);
        float2 r3 = unpack2(acc2[u][3]);
        const int t = t0 + ty*16 + 2*u;
        *reinterpret_cast<float4*>(base + (size_t)t*ND + n0 + tx*4) =
            make_float4(r0.x, r1.x, r2.x, r3.x);
        *reinterpret_cast<float4*>(base + (size_t)(t+1)*ND + n0 + tx*4) =
            make_float4(r0.y, r1.y, r2.y, r3.y);
    }
}

// ---------------- K5: reduce 4 partials, remap (t,n) -> out[b,t,i] ---------
__global__ __launch_bounds__(256) void k5_reduce(float* __restrict__ out)
{
    const int base_e = (blockIdx.x*blockDim.x + threadIdx.x) * 2;
    const size_t step = (size_t)(S*ND)/4;
#pragma unroll
    for (int q = 0; q < 2; ++q) {
        const int e  = base_e + q;
        const int n4 = e % (ND/4);
        const int t  = e / (ND/4);
        const int n  = n4 * 4;
        const int b  = n / D, i = n % D;
        const float4* p = reinterpret_cast<const float4*>(g_part) + e;
        float4 a = p[0];
#pragma unroll
        for (int zz = 1; zz < KSPLIT; ++zz) {
            float4 qv = p[zz*step];
            a.x += qv.x; a.y += qv.y; a.z += qv.z; a.w += qv.w;
        }
        *reinterpret_cast<float4*>(out + (size_t)b*(S*D) + (size_t)t*D + i) = a;
    }
}

// ---------------- launch ----------------------------------------------------
extern "C" void kernel_launch(void* const* d_in, const int* in_sizes, int n_in,
                              void* d_out, int out_size)
{
    const float* x     = (const float*)d_in[0];   // (8,1024,96)
    const float* M     = (const float*)d_in[1];   // (96,96)
    const float* P     = (const float*)d_in[2];   // (96,96,8)
    const float* L     = (const float*)d_in[3];   // (1024,1024)
    const float* gamma = (const float*)d_in[4];   // (96)
    const float* beta  = (const float*)d_in[5];   // (96)
    float* out = (float*)d_out;                   // (8,1024,96)

    k2_basis <<<(MTOT*(S/SCHUNK))/256, 256>>>(P);            // 576 blocks
    k13_fused<<<S, 768>>>(x, M, gamma, beta);                // 1024 blocks
    k4_gemm  <<<dim3(ND/BN, S/BT, KSPLIT), 256>>>(L);        // 192 blocks
    k5_reduce<<<(S*ND/8)/256, 256>>>(out);                   // 384 blocks
}

// round 9
// speedup vs baseline: 1.1123x; 1.1123x over previous
#include <cuda_runtime.h>
#include <cuda_fp16.h>
#include <cstdint>

#define B    8
#define S    1024
#define D    96
#define G    8
#define MTOT (D*D)          // 9216
#define ND   (B*D)          // 768
#define DPAD 100
#define LN_EPS 1e-5f
#define TWO_PI 6.283185307179586f

// ---------------- scratch (device globals; no allocation allowed) ----------
__device__ __half g_W   [S*MTOT];      // W[s, i*96+j] fp16            (18 MB)
__device__ float  g_A   [S*ND];        // (T+Z0) as A[s, b*96+i]       (3 MB)
__device__ float  g_part[4*S*ND];      // split-K partials             (12.6 MB)

// ---------------- packed f32x2 helpers (sm_103) -----------------------------
__device__ __forceinline__ unsigned long long splat2(float a) {
    unsigned long long r;
    asm("mov.b64 %0, {%1, %1};" : "=l"(r) : "f"(a));
    return r;
}
__device__ __forceinline__ void fma2(unsigned long long& d,
                                     unsigned long long a,
                                     unsigned long long b) {
    asm("fma.rn.f32x2 %0, %1, %2, %0;" : "+l"(d) : "l"(a), "l"(b));
}
__device__ __forceinline__ float2 unpack2(unsigned long long v) {
    float lo, hi;
    asm("mov.b64 {%0, %1}, %2;" : "=f"(lo), "=f"(hi) : "l"(v));
    return make_float2(lo, hi);
}

// ---------------- K2: W[s,m] = sum_g P[m*8+g] * cos(2*pi*s/(8m+g+2)) -------
#define SCHUNK 64
__global__ void k2_basis(const float* __restrict__ P)
{
    const int gidx  = blockIdx.x*blockDim.x + threadIdx.x;
    const int m     = gidx % MTOT;
    const int chunk = gidx / MTOT;
    const int s0    = chunk * SCHUNK;

    float kg[G], c0[G], c1[G], Pv[G];
#pragma unroll
    for (int g = 0; g < G; ++g) {
        const int p    = m*G + g + 2;
        const float fp = (float)p;
        kg[g] = 2.f * cosf(TWO_PI / fp);
        const int r0  = s0 % p;
        const int rm1 = (s0 + p - 1) % p;
        c1[g] = cosf(TWO_PI * (float)r0  / fp);
        c0[g] = cosf(TWO_PI * (float)rm1 / fp);
        Pv[g] = P[m*G + g];
    }

    __half* Wp = g_W + (size_t)s0*MTOT + m;
    for (int s = 0; s < SCHUNK; ++s) {
        float w = 0.f;
#pragma unroll
        for (int g = 0; g < G; ++g) w = fmaf(Pv[g], c1[g], w);
        Wp[(size_t)s*MTOT] = __float2half(w);
#pragma unroll
        for (int g = 0; g < G; ++g) {
            const float cn = fmaf(kg[g], c1[g], -c0[g]);
            c0[g] = c1[g];
            c1[g] = cn;
        }
    }
}

// ---------------- K13: fused project + LN + per-s mixing + residual --------
// thread layout tid = i*8 + b: smem reads broadcast within warps.
__global__ __launch_bounds__(768) void k13_fused(const float* __restrict__ x,
                                                 const float* __restrict__ M,
                                                 const float* __restrict__ gamma,
                                                 const float* __restrict__ beta)
{
    const int s   = blockIdx.x;
    const int tid = threadIdx.x;
    const int i   = tid >> 3;          // 0..95
    const int b   = tid & 7;           // 0..7

    __shared__ __align__(16) float sBuf[D*DPAD];    // M rows, then W rows (padded)
    __shared__ __align__(16) float sx  [B*DPAD];
    __shared__ __align__(16) float sZ  [B*DPAD];
    __shared__ float sS1[24][8], sS2[24][8];

    // prefetch W row-chunk as fp16 pairs (LDGs fly during phase 1)
    __half2 wreg[6];
    const __half2* Wp = reinterpret_cast<const __half2*>(g_W + (size_t)s*MTOT);
#pragma unroll
    for (int r = 0; r < 6; ++r) wreg[r] = Wp[tid + r*768];

    {
        const int bb = tid / D, jj = tid % D;
        sx[bb*DPAD + jj] = x[((size_t)bb*S + s)*D + jj];
    }
#pragma unroll
    for (int r = 0; r < 12; ++r) {
        const int f = tid + r*768;
        sBuf[(f / D)*DPAD + (f % D)] = M[f];
    }
    __syncthreads();

    // Z0[b,i] = dot(M[i,:], x[b,:]) — broadcast-friendly smem reads
    float z0 = 0.f;
    {
        const float4* mr = reinterpret_cast<const float4*>(sBuf + i*DPAD);
        const float4* xr = reinterpret_cast<const float4*>(sx + b*DPAD);
#pragma unroll
        for (int j4 = 0; j4 < D/4; ++j4) {
            const float4 m4 = mr[j4];
            const float4 x4 = xr[j4];
            z0 = fmaf(m4.x, x4.x, z0);
            z0 = fmaf(m4.y, x4.y, z0);
            z0 = fmaf(m4.z, x4.z, z0);
            z0 = fmaf(m4.w, x4.w, z0);
        }
    }

    // LayerNorm over i per b: i-bits in lane are bits 3,4
    float s1 = z0, s2 = z0*z0;
    s1 += __shfl_xor_sync(0xffffffffu, s1, 8);
    s2 += __shfl_xor_sync(0xffffffffu, s2, 8);
    s1 += __shfl_xor_sync(0xffffffffu, s1, 16);
    s2 += __shfl_xor_sync(0xffffffffu, s2, 16);
    const int w = tid >> 5, lane = tid & 31;
    if (lane < 8) { sS1[w][lane] = s1; sS2[w][lane] = s2; }
    __syncthreads();
    float t1 = 0.f, t2 = 0.f;
#pragma unroll
    for (int ww = 0; ww < 24; ++ww) { t1 += sS1[ww][b]; t2 += sS2[ww][b]; }
    const float mu  = t1 * (1.f/D);
    const float rstd = rsqrtf(t2 * (1.f/D) - mu*mu + LN_EPS);
    sZ[b*DPAD + i] = (z0 - mu)*rstd*gamma[i] + beta[i];

    // overwrite sBuf with W rows (fp16 -> f32, padded row-major)
#pragma unroll
    for (int r = 0; r < 6; ++r) {
        const int e0  = 2*(tid + r*768);
        const int row = e0 / D, col = e0 % D;
        const float2 v = __half22float2(wreg[r]);
        sBuf[row*DPAD + col]     = v.x;
        sBuf[row*DPAD + col + 1] = v.y;
    }
    __syncthreads();

    // T[b,i] = dot(W[s,i,:], Z[b,:]);  A = T + Z0
    float acc = 0.f;
    {
        const float4* wr = reinterpret_cast<const float4*>(sBuf + i*DPAD);
        const float4* zr = reinterpret_cast<const float4*>(sZ + b*DPAD);
#pragma unroll
        for (int j4 = 0; j4 < D/4; ++j4) {
            const float4 w4 = wr[j4];
            const float4 z4 = zr[j4];
            acc = fmaf(w4.x, z4.x, acc);
            acc = fmaf(w4.y, z4.y, acc);
            acc = fmaf(w4.z, z4.z, acc);
            acc = fmaf(w4.w, z4.w, acc);
        }
    }
    g_A[(size_t)s*ND + b*D + i] = acc + z0;
}

// ---------------- K4: split-K GEMM, 128x64 tile, 8x4 micro, f32x2 (R4 exact)
#define BT 128
#define BN 64
#define BK 16
#define KSPLIT 4
#define KCH (S/KSPLIT)     // 256
#define NIT (KCH/BK)       // 16
__global__ __launch_bounds__(256) void k4_gemm(const float* __restrict__ L)
{
    __shared__ __align__(16) float Ls[2][BK][BT];
    __shared__ __align__(16) float As[2][BK][BN];
    const int tid = threadIdx.x;
    const int n0  = blockIdx.x * BN;
    const int t0  = blockIdx.y * BT;
    const int z   = blockIdx.z;
    const int tx  = tid & 15;          // n micro (4 cols)
    const int ty  = tid >> 4;          // t micro (8 rows = 4 packed pairs)
    const int kbeg = z * KCH;

    const int lkk0 = tid >> 5,       lc0 = (tid & 31) * 4;
    const int lkk1 = (tid+256) >> 5, lc1 = lc0;
    const int akk  = tid >> 4,       ac  = (tid & 15) * 4;

    unsigned long long acc2[4][4];
#pragma unroll
    for (int u = 0; u < 4; ++u)
#pragma unroll
        for (int v = 0; v < 4; ++v) acc2[u][v] = 0ull;

    float4 pL0, pL1, pA;
    pL0 = *reinterpret_cast<const float4*>(&L[(size_t)(kbeg+lkk0)*S + t0 + lc0]);
    pL1 = *reinterpret_cast<const float4*>(&L[(size_t)(kbeg+lkk1)*S + t0 + lc1]);
    pA  = *reinterpret_cast<const float4*>(&g_A[(size_t)(kbeg+akk)*ND + n0 + ac]);
    *reinterpret_cast<float4*>(&Ls[0][lkk0][lc0]) = pL0;
    *reinterpret_cast<float4*>(&Ls[0][lkk1][lc1]) = pL1;
    *reinterpret_cast<float4*>(&As[0][akk][ac])   = pA;
    __syncthreads();

    for (int it = 0; it < NIT; ++it) {
        const int cur = it & 1;
        if (it + 1 < NIT) {
            const int ks = kbeg + (it+1)*BK;
            pL0 = *reinterpret_cast<const float4*>(&L[(size_t)(ks+lkk0)*S + t0 + lc0]);
            pL1 = *reinterpret_cast<const float4*>(&L[(size_t)(ks+lkk1)*S + t0 + lc1]);
            pA  = *reinterpret_cast<const float4*>(&g_A[(size_t)(ks+akk)*ND + n0 + ac]);
        }
#pragma unroll
        for (int kk = 0; kk < BK; ++kk) {
            const ulonglong2 lp0 =
                *reinterpret_cast<const ulonglong2*>(&Ls[cur][kk][ty*8]);
            const ulonglong2 lp1 =
                *reinterpret_cast<const ulonglong2*>(&Ls[cur][kk][ty*8+4]);
            const unsigned long long lp[4] = {lp0.x, lp0.y, lp1.x, lp1.y};
            const float4 a4 = *reinterpret_cast<const float4*>(&As[cur][kk][tx*4]);
            const unsigned long long ap[4] =
                {splat2(a4.x), splat2(a4.y), splat2(a4.z), splat2(a4.w)};
#pragma unroll
            for (int u = 0; u < 4; ++u)
#pragma unroll
                for (int v = 0; v < 4; ++v)
                    fma2(acc2[u][v], lp[u], ap[v]);
        }
        if (it + 1 < NIT) {
            const int nxt = cur ^ 1;
            *reinterpret_cast<float4*>(&Ls[nxt][lkk0][lc0]) = pL0;
            *reinterpret_cast<float4*>(&Ls[nxt][lkk1][lc1]) = pL1;
            *reinterpret_cast<float4*>(&As[nxt][akk][ac])   = pA;
        }
        __syncthreads();
    }

    float* base = g_part + (size_t)z*(S*ND);
#pragma unroll
    for (int u = 0; u < 4; ++u) {
        float2 r0 = unpack2(acc2[u][0]);
        float2 r1 = unpack2(acc2[u][1]);
        float2 r2 = unpack2(acc2[u][2]);
        float2 r3 = unpack2(acc2[u][3]);
        const int t = t0 + ty*8 + 2*u;
        *reinterpret_cast<float4*>(base + (size_t)t*ND + n0 + tx*4) =
            make_float4(r0.x, r1.x, r2.x, r3.x);
        *reinterpret_cast<float4*>(base + (size_t)(t+1)*ND + n0 + tx*4) =
            make_float4(r0.y, r1.y, r2.y, r3.y);
    }
}

// ---------------- K5: reduce 4 partials, remap (t,n) -> out[b,t,i] ---------
__global__ __launch_bounds__(256) void k5_reduce(float* __restrict__ out)
{
    const int base_e = (blockIdx.x*blockDim.x + threadIdx.x) * 2;
    const size_t step = (size_t)(S*ND)/4;
#pragma unroll
    for (int q = 0; q < 2; ++q) {
        const int e  = base_e + q;
        const int n4 = e % (ND/4);
        const int t  = e / (ND/4);
        const int n  = n4 * 4;
        const int b  = n / D, i = n % D;
        const float4* p = reinterpret_cast<const float4*>(g_part) + e;
        float4 a = p[0];
#pragma unroll
        for (int zz = 1; zz < KSPLIT; ++zz) {
            float4 qv = p[zz*step];
            a.x += qv.x; a.y += qv.y; a.z += qv.z; a.w += qv.w;
        }
        *reinterpret_cast<float4*>(out + (size_t)b*(S*D) + (size_t)t*D + i) = a;
    }
}

// ---------------- launch ----------------------------------------------------
extern "C" void kernel_launch(void* const* d_in, const int* in_sizes, int n_in,
                              void* d_out, int out_size)
{
    const float* x     = (const float*)d_in[0];   // (8,1024,96)
    const float* M     = (const float*)d_in[1];   // (96,96)
    const float* P     = (const float*)d_in[2];   // (96,96,8)
    const float* L     = (const float*)d_in[3];   // (1024,1024)
    const float* gamma = (const float*)d_in[4];   // (96)
    const float* beta  = (const float*)d_in[5];   // (96)
    float* out = (float*)d_out;                   // (8,1024,96)

    k2_basis <<<(MTOT*(S/SCHUNK))/256, 256>>>(P);            // 576 blocks
    k13_fused<<<S, 768>>>(x, M, gamma, beta);                // 1024 blocks
    k4_gemm  <<<dim3(ND/BN, S/BT, KSPLIT), 256>>>(L);        // 384 blocks
    k5_reduce<<<(S*ND/8)/256, 256>>>(out);                   // 384 blocks
}